// round 11
// baseline (speedup 1.0000x reference)
#include <cuda_runtime.h>
#include <cuda_bf16.h>
#include <cstdint>

#define NN 50000
#define NE 600000
#define FD 128
#define OUTC 64
#define MTILE 128
#define NTILES ((NN + MTILE - 1) / MTILE)   // 391
#define NNPAD (NTILES * MTILE)              // 50048
#define CHUNKE 16                            // edges per warp in row scatter

// ---------------- scratch (static device globals, zero-initialized) --------
__device__ float g_deg[NN];
__device__ float g_dis[NN];
__device__ int   g_cnt[NN];
__device__ int   g_fill[NN];
__device__ int4  g_edge[NE];                  // {row, bitcast(coef), col, 0} sorted by ROW
__device__ float g_buf[(size_t)NNPAD * FD];   // aggregation output (padded rows stay 0)
__device__ float g_h[(size_t)NN * FD];        // hidden activations
__device__ __nv_bfloat16 g_wimg_hi[2][16384]; // weight bf16 images, [n*128+k]
__device__ __nv_bfloat16 g_wimg_lo[2][16384];

// ---------------- mma / ldmatrix helpers (base sm_100 features) -------------
__device__ __forceinline__ uint32_t smem_u32(const void* p) {
    uint32_t a;
    asm("{ .reg .u64 t; cvta.to.shared.u64 t, %1; cvt.u32.u64 %0, t; }" : "=r"(a) : "l"(p));
    return a;
}
__device__ __forceinline__ void ldsm_x4(uint32_t* r, uint32_t addr) {
    asm volatile("ldmatrix.sync.aligned.m8n8.x4.shared.b16 {%0,%1,%2,%3}, [%4];"
        : "=r"(r[0]), "=r"(r[1]), "=r"(r[2]), "=r"(r[3]) : "r"(addr));
}
__device__ __forceinline__ void ldsm_x2(uint32_t* r, uint32_t addr) {
    asm volatile("ldmatrix.sync.aligned.m8n8.x2.shared.b16 {%0,%1}, [%2];"
        : "=r"(r[0]), "=r"(r[1]) : "r"(addr));
}
__device__ __forceinline__ void mma16816(float* c, const uint32_t* a, const uint32_t* b) {
    asm volatile("mma.sync.aligned.m16n8k16.row.col.f32.bf16.bf16.f32 "
        "{%0,%1,%2,%3}, {%4,%5,%6,%7}, {%8,%9}, {%0,%1,%2,%3};"
        : "+f"(c[0]), "+f"(c[1]), "+f"(c[2]), "+f"(c[3])
        : "r"(a[0]), "r"(a[1]), "r"(a[2]), "r"(a[3]), "r"(b[0]), "r"(b[1]));
}

// ---------------------------------------------------------------------------
// CSR build keyed by ROW: init -> hist (cnt by row, deg by col) -> scan -> fill
// ALL NE edges kept; self-loops carry coef = 0 (exact).
// ---------------------------------------------------------------------------
__global__ void k_init() {
    int i = blockIdx.x * blockDim.x + threadIdx.x;
    if (i < NN) { g_deg[i] = 1.0f; g_cnt[i] = 0; }
}

__global__ void k_hist(const int* __restrict__ row, const int* __restrict__ col,
                       const float* __restrict__ ew) {
    int e = blockIdx.x * blockDim.x + threadIdx.x;
    if (e >= NE) return;
    int r = row[e], c = col[e];
    atomicAdd(&g_cnt[r], 1);                       // slot count by SOURCE row
    if (r != c) atomicAdd(&g_deg[c], ew[e]);       // degree by destination
}

#define SCAN_T 1024
#define SCHUNK 49   // 1024*49 = 50176 >= NN

__global__ void k_scan() {
    __shared__ int ssum[SCAN_T];
    int t = threadIdx.x;
    int beg = t * SCHUNK;
    int end = beg + SCHUNK; if (end > NN) end = NN;
    int s = 0;
    for (int i = beg; i < end; i++) s += g_cnt[i];
    ssum[t] = s;
    __syncthreads();
    for (int off = 1; off < SCAN_T; off <<= 1) {
        int v = (t >= off) ? ssum[t - off] : 0;
        __syncthreads();
        ssum[t] += v;
        __syncthreads();
    }
    int base = (t == 0) ? 0 : ssum[t - 1];
    for (int i = beg; i < end; i++) {
        g_fill[i] = base;
        base += g_cnt[i];
        g_dis[i] = rsqrtf(g_deg[i]);
    }
}

__global__ void k_fill(const int* __restrict__ row, const int* __restrict__ col,
                       const float* __restrict__ ew) {
    int e = blockIdx.x * blockDim.x + threadIdx.x;
    if (e >= NE) return;
    int r = row[e], c = col[e];
    float coef = (r == c) ? 0.0f : g_dis[r] * ew[e] * g_dis[c];
    int pos = atomicAdd(&g_fill[r], 1);            // sorted by ROW
    g_edge[pos] = make_int4(r, __float_as_int(coef), c, 0);
}

// ---------------------------------------------------------------------------
// weight prep: fp32 W -> bf16 hi/lo images, plain [n][k] layout
// ---------------------------------------------------------------------------
__global__ void k_wprep(const float* __restrict__ W1, const float* __restrict__ Wmu,
                        const float* __restrict__ Wls) {
    int idx = blockIdx.x * blockDim.x + threadIdx.x;
    if (idx >= 2 * 16384) return;
    int layer = idx >> 14, e = idx & 16383;
    int n = e >> 7, k = e & 127;
    float w;
    if (layer == 0) w = W1[e];
    else            w = (n < 64) ? Wmu[n * 128 + k] : Wls[(n - 64) * 128 + k];
    __nv_bfloat16 hi = __float2bfloat16(w);
    __nv_bfloat16 lo = __float2bfloat16(w - __bfloat162float(hi));
    g_wimg_hi[layer][e] = hi;
    g_wimg_lo[layer][e] = lo;
}

// ---------------------------------------------------------------------------
// self-loop init: buf[i,:] = src[i,:] / deg[i]
// ---------------------------------------------------------------------------
template <bool FROM_H>
__global__ void k_selfinit(const float4* __restrict__ src_in) {
    int idx = blockIdx.x * blockDim.x + threadIdx.x;
    if (idx >= NN * 32) return;
    const float4* src = FROM_H ? (const float4*)g_h : src_in;
    int i = idx >> 5;
    float d = g_dis[i];
    float d2 = d * d;
    float4 v = src[idx];
    v.x *= d2; v.y *= d2; v.z *= d2; v.w *= d2;
    ((float4*)g_buf)[idx] = v;
}

// ---------------------------------------------------------------------------
// ROW-sorted scatter with source-row register reuse: a warp walks CHUNKE
// consecutive edges; the 512B src row load happens only when row changes
// (~1.3x per chunk, avg run = out-degree ~12). Writes stay fire-and-forget
// red.v4 (latency-tolerant; demonstrated ~6.5 TB/s combined in R1).
// ---------------------------------------------------------------------------
template <bool FROM_H>
__global__ void __launch_bounds__(256) k_rowscatter(const float4* __restrict__ src_in) {
    int warp = (blockIdx.x * blockDim.x + threadIdx.x) >> 5;
    int lane = threadIdx.x & 31;
    int s = warp * CHUNKE;
    if (s >= NE) return;
    int end = s + CHUNKE; if (end > NE) end = NE;
    const float4* src = FROM_H ? (const float4*)g_h : src_in;

    int cur = -1;
    float4 v = make_float4(0.f, 0.f, 0.f, 0.f);

    for (int e0 = s; e0 < end; e0 += 4) {
        int m = end - e0; if (m > 4) m = 4;
        int4 ed[4];
        #pragma unroll
        for (int i = 0; i < 4; i++)
            if (i < m) ed[i] = g_edge[e0 + i];
        #pragma unroll
        for (int i = 0; i < 4; i++) {
            if (i < m) {
                if (ed[i].x != cur) {
                    v = __ldg(&src[(size_t)ed[i].x * 32 + lane]);
                    cur = ed[i].x;
                }
                float cf = __int_as_float(ed[i].y);
                float f0 = v.x * cf, f1 = v.y * cf, f2 = v.z * cf, f3 = v.w * cf;
                float* dst = g_buf + (size_t)ed[i].z * FD + lane * 4;
                asm volatile("red.global.add.v4.f32 [%0], {%1,%2,%3,%4};"
                             :: "l"(dst), "f"(f0), "f"(f1), "f"(f2), "f"(f3)
                             : "memory");
            }
        }
    }
}

// ---------------------------------------------------------------------------
// HMMA GEMM (R6 proven): out[128-tile,128] = buf_tile @ W^T (+bias, opt relu)
// ---------------------------------------------------------------------------
#define APITCH 136
#define TILE_B (128 * APITCH * 2)   // 34816
#define SM_AHI 1024
#define SM_ALO (SM_AHI + TILE_B)
#define SM_BHI (SM_ALO + TILE_B)
#define SM_BLO (SM_BHI + TILE_B)
#define SM_TOTAL (SM_BLO + TILE_B)
#define EPI_PITCH 129

template <int MODE>
__global__ void __launch_bounds__(256) k_mmagemm(const float* __restrict__ ba,
                                                 const float* __restrict__ bb,
                                                 float* __restrict__ outA,
                                                 float* __restrict__ outB) {
    extern __shared__ char smem[];
    uint32_t sb = smem_u32(smem);
    int tid = threadIdx.x;
    int wid = tid >> 5;
    int lane = tid & 31;
    int row0 = blockIdx.x * MTILE;

    float* sbias = (float*)smem;
    if (tid < 128) {
        if (MODE == 0) sbias[tid] = ba[tid];
        else           sbias[tid] = (tid < 64) ? ba[tid] : bb[tid - 64];
    }

    for (int i = tid; i < 128 * 16; i += 256) {
        int n = i >> 4, seg = i & 15;
        uint32_t doff = (uint32_t)n * (APITCH * 2) + seg * 16;
        *(uint4*)(smem + SM_BHI + doff) = ((const uint4*)g_wimg_hi[MODE])[i];
        *(uint4*)(smem + SM_BLO + doff) = ((const uint4*)g_wimg_lo[MODE])[i];
    }

    for (int it = tid; it < 128 * 32; it += 256) {
        int row = it >> 5, seg = it & 31;
        float4 v = ((const float4*)(g_buf + (size_t)(row0 + row) * FD))[seg];
        __nv_bfloat16 h0 = __float2bfloat16(v.x), h1 = __float2bfloat16(v.y);
        __nv_bfloat16 h2 = __float2bfloat16(v.z), h3 = __float2bfloat16(v.w);
        __nv_bfloat16 l0 = __float2bfloat16(v.x - __bfloat162float(h0));
        __nv_bfloat16 l1 = __float2bfloat16(v.y - __bfloat162float(h1));
        __nv_bfloat16 l2 = __float2bfloat16(v.z - __bfloat162float(h2));
        __nv_bfloat16 l3 = __float2bfloat16(v.w - __bfloat162float(h3));
        uint32_t doff = (uint32_t)row * (APITCH * 2) + seg * 8;
        __nv_bfloat162 hv0(h0, h1), hv1(h2, h3), lv0(l0, l1), lv1(l2, l3);
        *(__nv_bfloat162*)(smem + SM_AHI + doff) = hv0;
        *(__nv_bfloat162*)(smem + SM_AHI + doff + 4) = hv1;
        *(__nv_bfloat162*)(smem + SM_ALO + doff) = lv0;
        *(__nv_bfloat162*)(smem + SM_ALO + doff + 4) = lv1;
    }
    __syncthreads();

    float acc[16][4];
    #pragma unroll
    for (int nt = 0; nt < 16; nt++)
        #pragma unroll
        for (int i = 0; i < 4; i++) acc[nt][i] = 0.0f;

    int ar = lane & 15, acg = lane >> 4;
    uint32_t a_base = (uint32_t)(16 * wid + ar) * (APITCH * 2) + acg * 16;
    int bn = lane & 7, bkg = (lane >> 3) & 1;

    #pragma unroll
    for (int kc = 0; kc < 8; kc++) {
        uint32_t a_hi[4], a_lo[4];
        uint32_t aoff = a_base + kc * 32;
        ldsm_x4(a_hi, sb + SM_AHI + aoff);
        ldsm_x4(a_lo, sb + SM_ALO + aoff);
        #pragma unroll
        for (int nt = 0; nt < 16; nt++) {
            uint32_t boff = (uint32_t)(nt * 8 + bn) * (APITCH * 2) + kc * 32 + bkg * 16;
            uint32_t b_hi[2], b_lo[2];
            ldsm_x2(b_hi, sb + SM_BHI + boff);
            ldsm_x2(b_lo, sb + SM_BLO + boff);
            mma16816(acc[nt], a_hi, b_hi);
            mma16816(acc[nt], a_hi, b_lo);
            mma16816(acc[nt], a_lo, b_hi);
        }
    }
    __syncthreads();

    float* epi = (float*)(smem + SM_AHI);
    int g = lane >> 2, cp = (lane & 3) * 2;
    #pragma unroll
    for (int nt = 0; nt < 16; nt++) {
        int colb = nt * 8 + cp;
        epi[(16 * wid + g) * EPI_PITCH + colb]     = acc[nt][0];
        epi[(16 * wid + g) * EPI_PITCH + colb + 1] = acc[nt][1];
        epi[(16 * wid + g + 8) * EPI_PITCH + colb]     = acc[nt][2];
        epi[(16 * wid + g + 8) * EPI_PITCH + colb + 1] = acc[nt][3];
    }
    __syncthreads();

    for (int it = tid; it < 128 * 128; it += 256) {
        int row = it >> 7, col = it & 127;
        int grow = row0 + row;
        if (grow >= NN) continue;
        float v = epi[row * EPI_PITCH + col] + sbias[col];
        if (MODE == 0) {
            g_h[(size_t)grow * FD + col] = fmaxf(v, 0.0f);
        } else {
            if (col < 64) outA[(size_t)grow * OUTC + col] = v;
            else          outB[(size_t)grow * OUTC + col - 64] = v;
        }
    }
}

// ---------------------------------------------------------------------------
extern "C" void kernel_launch(void* const* d_in, const int* in_sizes, int n_in,
                              void* d_out, int out_size) {
    const float* x   = (const float*)d_in[0];
    const int*   ei  = (const int*)d_in[1];
    const float* ew  = (const float*)d_in[2];
    const float* W1  = (const float*)d_in[3];
    const float* b1  = (const float*)d_in[4];
    const float* Wmu = (const float*)d_in[5];
    const float* bmu = (const float*)d_in[6];
    const float* Wls = (const float*)d_in[7];
    const float* bls = (const float*)d_in[8];
    const int* row = ei;
    const int* col = ei + NE;

    float* mu = (float*)d_out;
    float* ls = mu + (size_t)NN * OUTC;

    static bool s_attr = false;
    if (!s_attr) {
        cudaFuncSetAttribute(k_mmagemm<0>, cudaFuncAttributeMaxDynamicSharedMemorySize, SM_TOTAL);
        cudaFuncSetAttribute(k_mmagemm<1>, cudaFuncAttributeMaxDynamicSharedMemorySize, SM_TOTAL);
        s_attr = true;
    }

    int tb = 256;
    int gN  = (NN + tb - 1) / tb;
    int gE  = (NE + tb - 1) / tb;
    int gF4 = (NN * 32 + tb - 1) / tb;
    int nWarps = (NE + CHUNKE - 1) / CHUNKE;
    int gSeg = (nWarps * 32 + tb - 1) / tb;

    // row-CSR build (amortized over both layers)
    k_init<<<gN, tb>>>();
    k_hist<<<gE, tb>>>(row, col, ew);
    k_scan<<<1, SCAN_T>>>();
    k_fill<<<gE, tb>>>(row, col, ew);
    k_wprep<<<(2 * 16384 + tb - 1) / tb, tb>>>(W1, Wmu, Wls);

    // layer 1
    k_selfinit<false><<<gF4, tb>>>((const float4*)x);
    k_rowscatter<false><<<gSeg, tb>>>((const float4*)x);
    k_mmagemm<0><<<NTILES, tb, SM_TOTAL>>>(b1, nullptr, nullptr, nullptr);

    // layer 2
    k_selfinit<true><<<gF4, tb>>>(nullptr);
    k_rowscatter<true><<<gSeg, tb>>>(nullptr);
    k_mmagemm<1><<<NTILES, tb, SM_TOTAL>>>(bmu, bls, mu, ls);
}

// round 13
// speedup vs baseline: 1.1989x; 1.1989x over previous
#include <cuda_runtime.h>
#include <cuda_bf16.h>
#include <cuda_fp16.h>
#include <cstdint>

#define NN 50000
#define NE 600000
#define FD 128
#define OUTC 64
#define MTILE 128
#define NTILES ((NN + MTILE - 1) / MTILE)   // 391
#define NNPAD (NTILES * MTILE)              // 50048

// ---------------- scratch (static device globals, zero-initialized) --------
__device__ float g_deg[NN];
__device__ float g_dis[NN];
__device__ float g_buf[(size_t)NNPAD * FD];   // aggregation output (padded rows stay 0)
__device__ float g_h[(size_t)NN * FD];        // hidden activations (fp32)
__device__ __half g_xh[(size_t)NN * FD];      // fp16 image of x   (layer-1 scatter reads)
__device__ __half g_hh[(size_t)NN * FD];      // fp16 image of h   (layer-2 scatter reads)
__device__ __nv_bfloat16 g_wimg_hi[2][16384]; // weight bf16 images, [n*128+k]
__device__ __nv_bfloat16 g_wimg_lo[2][16384];

// ---------------- mma / ldmatrix helpers (base sm_100 features) -------------
__device__ __forceinline__ uint32_t smem_u32(const void* p) {
    uint32_t a;
    asm("{ .reg .u64 t; cvta.to.shared.u64 t, %1; cvt.u32.u64 %0, t; }" : "=r"(a) : "l"(p));
    return a;
}
__device__ __forceinline__ void ldsm_x4(uint32_t* r, uint32_t addr) {
    asm volatile("ldmatrix.sync.aligned.m8n8.x4.shared.b16 {%0,%1,%2,%3}, [%4];"
        : "=r"(r[0]), "=r"(r[1]), "=r"(r[2]), "=r"(r[3]) : "r"(addr));
}
__device__ __forceinline__ void ldsm_x2(uint32_t* r, uint32_t addr) {
    asm volatile("ldmatrix.sync.aligned.m8n8.x2.shared.b16 {%0,%1}, [%2];"
        : "=r"(r[0]), "=r"(r[1]) : "r"(addr));
}
__device__ __forceinline__ void mma16816(float* c, const uint32_t* a, const uint32_t* b) {
    asm volatile("mma.sync.aligned.m16n8k16.row.col.f32.bf16.bf16.f32 "
        "{%0,%1,%2,%3}, {%4,%5,%6,%7}, {%8,%9}, {%0,%1,%2,%3};"
        : "+f"(c[0]), "+f"(c[1]), "+f"(c[2]), "+f"(c[3])
        : "r"(a[0]), "r"(a[1]), "r"(a[2]), "r"(a[3]), "r"(b[0]), "r"(b[1]));
}

// ---------------------------------------------------------------------------
// degree / norm kernels
// ---------------------------------------------------------------------------
__global__ void k_deg_init() {
    int i = blockIdx.x * blockDim.x + threadIdx.x;
    if (i < NN) g_deg[i] = 1.0f;
}
__global__ void k_deg_edges(const int* __restrict__ row, const int* __restrict__ col,
                            const float* __restrict__ ew) {
    int e = blockIdx.x * blockDim.x + threadIdx.x;
    if (e >= NE) return;
    int r = row[e], c = col[e];
    if (r != c) atomicAdd(&g_deg[c], ew[e]);
}
__global__ void k_dis() {
    int i = blockIdx.x * blockDim.x + threadIdx.x;
    if (i < NN) g_dis[i] = rsqrtf(g_deg[i]);
}

// ---------------------------------------------------------------------------
// x -> fp16 image (one 8B store per thread)
// ---------------------------------------------------------------------------
__global__ void k_xhalf(const float4* __restrict__ x) {
    int idx = blockIdx.x * blockDim.x + threadIdx.x;   // over NN*32 float4s
    if (idx >= NN * 32) return;
    float4 v = x[idx];
    union { __half2 h2[2]; uint2 u; } pk;
    pk.h2[0] = __floats2half2_rn(v.x, v.y);
    pk.h2[1] = __floats2half2_rn(v.z, v.w);
    ((uint2*)g_xh)[idx] = pk.u;
}

// ---------------------------------------------------------------------------
// weight prep: fp32 W -> bf16 hi/lo images, plain [n][k] layout
// ---------------------------------------------------------------------------
__global__ void k_wprep(const float* __restrict__ W1, const float* __restrict__ Wmu,
                        const float* __restrict__ Wls) {
    int idx = blockIdx.x * blockDim.x + threadIdx.x;
    if (idx >= 2 * 16384) return;
    int layer = idx >> 14, e = idx & 16383;
    int n = e >> 7, k = e & 127;
    float w;
    if (layer == 0) w = W1[e];
    else            w = (n < 64) ? Wmu[n * 128 + k] : Wls[(n - 64) * 128 + k];
    __nv_bfloat16 hi = __float2bfloat16(w);
    __nv_bfloat16 lo = __float2bfloat16(w - __bfloat162float(hi));
    g_wimg_hi[layer][e] = hi;
    g_wimg_lo[layer][e] = lo;
}

// ---------------------------------------------------------------------------
// self-loop init (exact fp32): buf[i,:] = src[i,:] / deg[i]
// ---------------------------------------------------------------------------
template <bool FROM_H>
__global__ void k_selfinit(const float4* __restrict__ src_in) {
    int idx = blockIdx.x * blockDim.x + threadIdx.x;
    if (idx >= NN * 32) return;
    const float4* src = FROM_H ? (const float4*)g_h : src_in;
    int i = idx >> 5;
    float d = g_dis[i];
    float d2 = d * d;
    float4 v = src[idx];
    v.x *= d2; v.y *= d2; v.z *= d2; v.w *= d2;
    ((float4*)g_buf)[idx] = v;
}

// ---------------------------------------------------------------------------
// brute scatter (R6 structure), fp16 source reads: warp per edge, lane reads
// 4 halves (8B), converts, scales by fp32 coef, red.v4.f32 fire-and-forget.
// Read stream halves: 512B -> 256B per edge.
// ---------------------------------------------------------------------------
template <bool FROM_H>
__global__ void k_scatter(const int* __restrict__ row, const int* __restrict__ col,
                          const float* __restrict__ ew) {
    int gw = (blockIdx.x * blockDim.x + threadIdx.x) >> 5;
    int lane = threadIdx.x & 31;
    if (gw >= NE) return;
    int r = __ldg(&row[gw]);
    int c = __ldg(&col[gw]);
    if (r == c) return;  // add_remaining_self_loops zeroes existing self-loops
    float coef = g_dis[r] * __ldg(&ew[gw]) * g_dis[c];
    const uint2* src = (const uint2*)(FROM_H ? g_hh : g_xh);
    uint2 u = __ldg(&src[(size_t)r * 32 + lane]);
    union { uint32_t u; __half2 h; } a, b;
    a.u = u.x; b.u = u.y;
    float2 f0 = __half22float2(a.h);
    float2 f1 = __half22float2(b.h);
    float x0 = f0.x * coef, x1 = f0.y * coef, x2 = f1.x * coef, x3 = f1.y * coef;
    float* dst = g_buf + (size_t)c * FD + lane * 4;
    asm volatile("red.global.add.v4.f32 [%0], {%1,%2,%3,%4};"
                 :: "l"(dst), "f"(x0), "f"(x1), "f"(x2), "f"(x3)
                 : "memory");
}

// ---------------------------------------------------------------------------
// HMMA GEMM (R6 proven): out[128-tile,128] = buf_tile @ W^T (+bias, opt relu)
// MODE 0 epilogue additionally writes the fp16 image of h for layer-2 scatter.
// ---------------------------------------------------------------------------
#define APITCH 136
#define TILE_B (128 * APITCH * 2)   // 34816
#define SM_AHI 1024
#define SM_ALO (SM_AHI + TILE_B)
#define SM_BHI (SM_ALO + TILE_B)
#define SM_BLO (SM_BHI + TILE_B)
#define SM_TOTAL (SM_BLO + TILE_B)
#define EPI_PITCH 129

template <int MODE>
__global__ void __launch_bounds__(256) k_mmagemm(const float* __restrict__ ba,
                                                 const float* __restrict__ bb,
                                                 float* __restrict__ outA,
                                                 float* __restrict__ outB) {
    extern __shared__ char smem[];
    uint32_t sb = smem_u32(smem);
    int tid = threadIdx.x;
    int wid = tid >> 5;
    int lane = tid & 31;
    int row0 = blockIdx.x * MTILE;

    float* sbias = (float*)smem;
    if (tid < 128) {
        if (MODE == 0) sbias[tid] = ba[tid];
        else           sbias[tid] = (tid < 64) ? ba[tid] : bb[tid - 64];
    }

    for (int i = tid; i < 128 * 16; i += 256) {
        int n = i >> 4, seg = i & 15;
        uint32_t doff = (uint32_t)n * (APITCH * 2) + seg * 16;
        *(uint4*)(smem + SM_BHI + doff) = ((const uint4*)g_wimg_hi[MODE])[i];
        *(uint4*)(smem + SM_BLO + doff) = ((const uint4*)g_wimg_lo[MODE])[i];
    }

    for (int it = tid; it < 128 * 32; it += 256) {
        int row = it >> 5, seg = it & 31;
        float4 v = ((const float4*)(g_buf + (size_t)(row0 + row) * FD))[seg];
        __nv_bfloat16 h0 = __float2bfloat16(v.x), h1 = __float2bfloat16(v.y);
        __nv_bfloat16 h2 = __float2bfloat16(v.z), h3 = __float2bfloat16(v.w);
        __nv_bfloat16 l0 = __float2bfloat16(v.x - __bfloat162float(h0));
        __nv_bfloat16 l1 = __float2bfloat16(v.y - __bfloat162float(h1));
        __nv_bfloat16 l2 = __float2bfloat16(v.z - __bfloat162float(h2));
        __nv_bfloat16 l3 = __float2bfloat16(v.w - __bfloat162float(h3));
        uint32_t doff = (uint32_t)row * (APITCH * 2) + seg * 8;
        __nv_bfloat162 hv0(h0, h1), hv1(h2, h3), lv0(l0, l1), lv1(l2, l3);
        *(__nv_bfloat162*)(smem + SM_AHI + doff) = hv0;
        *(__nv_bfloat162*)(smem + SM_AHI + doff + 4) = hv1;
        *(__nv_bfloat162*)(smem + SM_ALO + doff) = lv0;
        *(__nv_bfloat162*)(smem + SM_ALO + doff + 4) = lv1;
    }
    __syncthreads();

    float acc[16][4];
    #pragma unroll
    for (int nt = 0; nt < 16; nt++)
        #pragma unroll
        for (int i = 0; i < 4; i++) acc[nt][i] = 0.0f;

    int ar = lane & 15, acg = lane >> 4;
    uint32_t a_base = (uint32_t)(16 * wid + ar) * (APITCH * 2) + acg * 16;
    int bn = lane & 7, bkg = (lane >> 3) & 1;

    #pragma unroll
    for (int kc = 0; kc < 8; kc++) {
        uint32_t a_hi[4], a_lo[4];
        uint32_t aoff = a_base + kc * 32;
        ldsm_x4(a_hi, sb + SM_AHI + aoff);
        ldsm_x4(a_lo, sb + SM_ALO + aoff);
        #pragma unroll
        for (int nt = 0; nt < 16; nt++) {
            uint32_t boff = (uint32_t)(nt * 8 + bn) * (APITCH * 2) + kc * 32 + bkg * 16;
            uint32_t b_hi[2], b_lo[2];
            ldsm_x2(b_hi, sb + SM_BHI + boff);
            ldsm_x2(b_lo, sb + SM_BLO + boff);
            mma16816(acc[nt], a_hi, b_hi);
            mma16816(acc[nt], a_hi, b_lo);
            mma16816(acc[nt], a_lo, b_hi);
        }
    }
    __syncthreads();

    float* epi = (float*)(smem + SM_AHI);
    int g = lane >> 2, cp = (lane & 3) * 2;
    #pragma unroll
    for (int nt = 0; nt < 16; nt++) {
        int colb = nt * 8 + cp;
        epi[(16 * wid + g) * EPI_PITCH + colb]     = acc[nt][0];
        epi[(16 * wid + g) * EPI_PITCH + colb + 1] = acc[nt][1];
        epi[(16 * wid + g + 8) * EPI_PITCH + colb]     = acc[nt][2];
        epi[(16 * wid + g + 8) * EPI_PITCH + colb + 1] = acc[nt][3];
    }
    __syncthreads();

    for (int it = tid; it < 128 * 128; it += 256) {
        int row = it >> 7, col = it & 127;
        int grow = row0 + row;
        if (grow >= NN) continue;
        float v = epi[row * EPI_PITCH + col] + sbias[col];
        if (MODE == 0) {
            float vr = fmaxf(v, 0.0f);
            g_h[(size_t)grow * FD + col] = vr;
            g_hh[(size_t)grow * FD + col] = __float2half_rn(vr);
        } else {
            if (col < 64) outA[(size_t)grow * OUTC + col] = v;
            else          outB[(size_t)grow * OUTC + col - 64] = v;
        }
    }
}

// ---------------------------------------------------------------------------
extern "C" void kernel_launch(void* const* d_in, const int* in_sizes, int n_in,
                              void* d_out, int out_size) {
    const float* x   = (const float*)d_in[0];
    const int*   ei  = (const int*)d_in[1];
    const float* ew  = (const float*)d_in[2];
    const float* W1  = (const float*)d_in[3];
    const float* b1  = (const float*)d_in[4];
    const float* Wmu = (const float*)d_in[5];
    const float* bmu = (const float*)d_in[6];
    const float* Wls = (const float*)d_in[7];
    const float* bls = (const float*)d_in[8];
    const int* row = ei;
    const int* col = ei + NE;

    float* mu = (float*)d_out;
    float* ls = mu + (size_t)NN * OUTC;

    static bool s_attr = false;
    if (!s_attr) {
        cudaFuncSetAttribute(k_mmagemm<0>, cudaFuncAttributeMaxDynamicSharedMemorySize, SM_TOTAL);
        cudaFuncSetAttribute(k_mmagemm<1>, cudaFuncAttributeMaxDynamicSharedMemorySize, SM_TOTAL);
        s_attr = true;
    }

    int tb = 256;
    int gN  = (NN + tb - 1) / tb;
    int gE  = (NE + tb - 1) / tb;
    int gF4 = (NN * 32 + tb - 1) / tb;
    int gEw = (NE * 32 + tb - 1) / tb;

    k_deg_init<<<gN, tb>>>();
    k_deg_edges<<<gE, tb>>>(row, col, ew);
    k_dis<<<gN, tb>>>();
    k_wprep<<<(2 * 16384 + tb - 1) / tb, tb>>>(W1, Wmu, Wls);
    k_xhalf<<<gF4, tb>>>((const float4*)x);

    // layer 1
    k_selfinit<false><<<gF4, tb>>>((const float4*)x);
    k_scatter<false><<<gEw, tb>>>(row, col, ew);
    k_mmagemm<0><<<NTILES, tb, SM_TOTAL>>>(b1, nullptr, nullptr, nullptr);

    // layer 2
    k_selfinit<true><<<gF4, tb>>>(nullptr);
    k_scatter<true><<<gEw, tb>>>(nullptr == nullptr ? row : row, col, ew);
    k_mmagemm<1><<<NTILES, tb, SM_TOTAL>>>(bmu, bls, mu, ls);
}

// round 15
// speedup vs baseline: 1.3056x; 1.0890x over previous
#include <cuda_runtime.h>
#include <cuda_bf16.h>
#include <cstdint>

#define NN 50000
#define NE 600000
#define FD 128
#define OUTC 64
#define MTILE 128
#define NTILES ((NN + MTILE - 1) / MTILE)   // 391
#define NNPAD (NTILES * MTILE)              // 50048

// ---------------- scratch (static device globals, zero-initialized) --------
__device__ float g_deg[NN];
__device__ float g_dis[NN];
__device__ float g_buf[(size_t)NNPAD * FD];   // aggregation buffer (padded rows stay 0)
__device__ float g_h[(size_t)NN * FD];        // hidden activations
__device__ __nv_bfloat16 g_wimg_hi[2][16384]; // weight bf16 images, [n*128+k]
__device__ __nv_bfloat16 g_wimg_lo[2][16384];

// ---------------- mma / ldmatrix helpers (base sm_100 features) -------------
__device__ __forceinline__ uint32_t smem_u32(const void* p) {
    uint32_t a;
    asm("{ .reg .u64 t; cvta.to.shared.u64 t, %1; cvt.u32.u64 %0, t; }" : "=r"(a) : "l"(p));
    return a;
}
__device__ __forceinline__ void ldsm_x4(uint32_t* r, uint32_t addr) {
    asm volatile("ldmatrix.sync.aligned.m8n8.x4.shared.b16 {%0,%1,%2,%3}, [%4];"
        : "=r"(r[0]), "=r"(r[1]), "=r"(r[2]), "=r"(r[3]) : "r"(addr));
}
__device__ __forceinline__ void ldsm_x2(uint32_t* r, uint32_t addr) {
    asm volatile("ldmatrix.sync.aligned.m8n8.x2.shared.b16 {%0,%1}, [%2];"
        : "=r"(r[0]), "=r"(r[1]) : "r"(addr));
}
__device__ __forceinline__ void mma16816(float* c, const uint32_t* a, const uint32_t* b) {
    asm volatile("mma.sync.aligned.m16n8k16.row.col.f32.bf16.bf16.f32 "
        "{%0,%1,%2,%3}, {%4,%5,%6,%7}, {%8,%9}, {%0,%1,%2,%3};"
        : "+f"(c[0]), "+f"(c[1]), "+f"(c[2]), "+f"(c[3])
        : "r"(a[0]), "r"(a[1]), "r"(a[2]), "r"(a[3]), "r"(b[0]), "r"(b[1]));
}

// ---------------------------------------------------------------------------
// degree kernels
// ---------------------------------------------------------------------------
__global__ void k_deg_init() {
    int i = blockIdx.x * blockDim.x + threadIdx.x;
    if (i < NN) g_deg[i] = 1.0f;
}
__global__ void k_deg_edges(const int* __restrict__ row, const int* __restrict__ col,
                            const float* __restrict__ ew) {
    int e = blockIdx.x * blockDim.x + threadIdx.x;
    if (e >= NE) return;
    int r = row[e], c = col[e];
    if (r != c) atomicAdd(&g_deg[c], ew[e]);
}

// ---------------------------------------------------------------------------
// fused prep: dis = rsqrt(deg) (written once per node) AND layer-1 self-term
// buf[i,:] = x[i,:] * dis^2
// ---------------------------------------------------------------------------
__global__ void k_prep(const float4* __restrict__ x) {
    int idx = blockIdx.x * blockDim.x + threadIdx.x;   // over NN*32 float4s
    if (idx >= NN * 32) return;
    int i = idx >> 5;
    float d = rsqrtf(g_deg[i]);
    if ((idx & 31) == 0) g_dis[i] = d;
    float d2 = d * d;
    float4 v = x[idx];
    v.x *= d2; v.y *= d2; v.z *= d2; v.w *= d2;
    ((float4*)g_buf)[idx] = v;
}

// ---------------------------------------------------------------------------
// brute scatter (R1/R6 proven): warp per edge, lane per float4, fire-and-forget
// red.v4.f32. This is at its structural floor (REDG issue ~0.85-1.3 cyc/lane).
// ---------------------------------------------------------------------------
template <bool FROM_H>
__global__ void k_scatter(const float4* __restrict__ src_in,
                          const int* __restrict__ row, const int* __restrict__ col,
                          const float* __restrict__ ew) {
    int gw = (blockIdx.x * blockDim.x + threadIdx.x) >> 5;
    int lane = threadIdx.x & 31;
    if (gw >= NE) return;
    int r = __ldg(&row[gw]);
    int c = __ldg(&col[gw]);
    if (r == c) return;  // add_remaining_self_loops zeroes existing self-loops
    float coef = g_dis[r] * __ldg(&ew[gw]) * g_dis[c];
    const float4* src = FROM_H ? (const float4*)g_h : src_in;
    float4 v = __ldg(&src[(size_t)r * 32 + lane]);
    float x0 = v.x * coef, x1 = v.y * coef, x2 = v.z * coef, x3 = v.w * coef;
    float* dst = g_buf + (size_t)c * FD + lane * 4;
    asm volatile("red.global.add.v4.f32 [%0], {%1,%2,%3,%4};"
                 :: "l"(dst), "f"(x0), "f"(x1), "f"(x2), "f"(x3)
                 : "memory");
}

// ---------------------------------------------------------------------------
// weight prep: fp32 W -> bf16 hi/lo images, plain [n][k] layout
// ---------------------------------------------------------------------------
__global__ void k_wprep(const float* __restrict__ W1, const float* __restrict__ Wmu,
                        const float* __restrict__ Wls) {
    int idx = blockIdx.x * blockDim.x + threadIdx.x;
    if (idx >= 2 * 16384) return;
    int layer = idx >> 14, e = idx & 16383;
    int n = e >> 7, k = e & 127;
    float w;
    if (layer == 0) w = W1[e];
    else            w = (n < 64) ? Wmu[n * 128 + k] : Wls[(n - 64) * 128 + k];
    __nv_bfloat16 hi = __float2bfloat16(w);
    __nv_bfloat16 lo = __float2bfloat16(w - __bfloat162float(hi));
    g_wimg_hi[layer][e] = hi;
    g_wimg_lo[layer][e] = lo;
}

// ---------------------------------------------------------------------------
// HMMA GEMM (R6 proven): out[128-tile,128] = buf_tile @ W^T (+bias, opt relu)
// MODE 0 epilogue ALSO writes the layer-2 self-term into g_buf (rows of this
// CTA's tile only — disjoint, and already consumed by its own prologue):
//   g_h = relu(v);  g_buf = relu(v) * dis^2
// ---------------------------------------------------------------------------
#define APITCH 136
#define TILE_B (128 * APITCH * 2)   // 34816
#define SM_AHI 1024
#define SM_ALO (SM_AHI + TILE_B)
#define SM_BHI (SM_ALO + TILE_B)
#define SM_BLO (SM_BHI + TILE_B)
#define SM_TOTAL (SM_BLO + TILE_B)
#define EPI_PITCH 129

template <int MODE>
__global__ void __launch_bounds__(256) k_mmagemm(const float* __restrict__ ba,
                                                 const float* __restrict__ bb,
                                                 float* __restrict__ outA,
                                                 float* __restrict__ outB) {
    extern __shared__ char smem[];
    uint32_t sb = smem_u32(smem);
    int tid = threadIdx.x;
    int wid = tid >> 5;
    int lane = tid & 31;
    int row0 = blockIdx.x * MTILE;

    float* sbias = (float*)smem;            // [0..512)
    float* sdis  = (float*)(smem + 512);    // [512..1024)
    if (tid < 128) {
        if (MODE == 0) sbias[tid] = ba[tid];
        else           sbias[tid] = (tid < 64) ? ba[tid] : bb[tid - 64];
    }
    if (MODE == 0) {
        for (int i = tid; i < 128; i += 256) {
            int gr = row0 + i;
            sdis[i] = (gr < NN) ? g_dis[gr] : 0.0f;
        }
    }

    for (int i = tid; i < 128 * 16; i += 256) {
        int n = i >> 4, seg = i & 15;
        uint32_t doff = (uint32_t)n * (APITCH * 2) + seg * 16;
        *(uint4*)(smem + SM_BHI + doff) = ((const uint4*)g_wimg_hi[MODE])[i];
        *(uint4*)(smem + SM_BLO + doff) = ((const uint4*)g_wimg_lo[MODE])[i];
    }

    for (int it = tid; it < 128 * 32; it += 256) {
        int row = it >> 5, seg = it & 31;
        float4 v = ((const float4*)(g_buf + (size_t)(row0 + row) * FD))[seg];
        __nv_bfloat16 h0 = __float2bfloat16(v.x), h1 = __float2bfloat16(v.y);
        __nv_bfloat16 h2 = __float2bfloat16(v.z), h3 = __float2bfloat16(v.w);
        __nv_bfloat16 l0 = __float2bfloat16(v.x - __bfloat162float(h0));
        __nv_bfloat16 l1 = __float2bfloat16(v.y - __bfloat162float(h1));
        __nv_bfloat16 l2 = __float2bfloat16(v.z - __bfloat162float(h2));
        __nv_bfloat16 l3 = __float2bfloat16(v.w - __bfloat162float(h3));
        uint32_t doff = (uint32_t)row * (APITCH * 2) + seg * 8;
        __nv_bfloat162 hv0(h0, h1), hv1(h2, h3), lv0(l0, l1), lv1(l2, l3);
        *(__nv_bfloat162*)(smem + SM_AHI + doff) = hv0;
        *(__nv_bfloat162*)(smem + SM_AHI + doff + 4) = hv1;
        *(__nv_bfloat162*)(smem + SM_ALO + doff) = lv0;
        *(__nv_bfloat162*)(smem + SM_ALO + doff + 4) = lv1;
    }
    __syncthreads();

    float acc[16][4];
    #pragma unroll
    for (int nt = 0; nt < 16; nt++)
        #pragma unroll
        for (int i = 0; i < 4; i++) acc[nt][i] = 0.0f;

    int ar = lane & 15, acg = lane >> 4;
    uint32_t a_base = (uint32_t)(16 * wid + ar) * (APITCH * 2) + acg * 16;
    int bn = lane & 7, bkg = (lane >> 3) & 1;

    #pragma unroll
    for (int kc = 0; kc < 8; kc++) {
        uint32_t a_hi[4], a_lo[4];
        uint32_t aoff = a_base + kc * 32;
        ldsm_x4(a_hi, sb + SM_AHI + aoff);
        ldsm_x4(a_lo, sb + SM_ALO + aoff);
        #pragma unroll
        for (int nt = 0; nt < 16; nt++) {
            uint32_t boff = (uint32_t)(nt * 8 + bn) * (APITCH * 2) + kc * 32 + bkg * 16;
            uint32_t b_hi[2], b_lo[2];
            ldsm_x2(b_hi, sb + SM_BHI + boff);
            ldsm_x2(b_lo, sb + SM_BLO + boff);
            mma16816(acc[nt], a_hi, b_hi);
            mma16816(acc[nt], a_hi, b_lo);
            mma16816(acc[nt], a_lo, b_hi);
        }
    }
    __syncthreads();

    float* epi = (float*)(smem + SM_AHI);
    int g = lane >> 2, cp = (lane & 3) * 2;
    #pragma unroll
    for (int nt = 0; nt < 16; nt++) {
        int colb = nt * 8 + cp;
        epi[(16 * wid + g) * EPI_PITCH + colb]     = acc[nt][0];
        epi[(16 * wid + g) * EPI_PITCH + colb + 1] = acc[nt][1];
        epi[(16 * wid + g + 8) * EPI_PITCH + colb]     = acc[nt][2];
        epi[(16 * wid + g + 8) * EPI_PITCH + colb + 1] = acc[nt][3];
    }
    __syncthreads();

    for (int it = tid; it < 128 * 128; it += 256) {
        int row = it >> 7, col = it & 127;
        int grow = row0 + row;
        if (grow >= NN) continue;
        float v = epi[row * EPI_PITCH + col] + sbias[col];
        if (MODE == 0) {
            float vr = fmaxf(v, 0.0f);
            float d = sdis[row];
            g_h[(size_t)grow * FD + col] = vr;
            g_buf[(size_t)grow * FD + col] = vr * d * d;   // layer-2 self-term
        } else {
            if (col < 64) outA[(size_t)grow * OUTC + col] = v;
            else          outB[(size_t)grow * OUTC + col - 64] = v;
        }
    }
}

// ---------------------------------------------------------------------------
extern "C" void kernel_launch(void* const* d_in, const int* in_sizes, int n_in,
                              void* d_out, int out_size) {
    const float* x   = (const float*)d_in[0];
    const int*   ei  = (const int*)d_in[1];
    const float* ew  = (const float*)d_in[2];
    const float* W1  = (const float*)d_in[3];
    const float* b1  = (const float*)d_in[4];
    const float* Wmu = (const float*)d_in[5];
    const float* bmu = (const float*)d_in[6];
    const float* Wls = (const float*)d_in[7];
    const float* bls = (const float*)d_in[8];
    const int* row = ei;
    const int* col = ei + NE;

    float* mu = (float*)d_out;
    float* ls = mu + (size_t)NN * OUTC;

    static bool s_attr = false;
    if (!s_attr) {
        cudaFuncSetAttribute(k_mmagemm<0>, cudaFuncAttributeMaxDynamicSharedMemorySize, SM_TOTAL);
        cudaFuncSetAttribute(k_mmagemm<1>, cudaFuncAttributeMaxDynamicSharedMemorySize, SM_TOTAL);
        s_attr = true;
    }

    int tb = 256;
    int gN  = (NN + tb - 1) / tb;
    int gE  = (NE + tb - 1) / tb;
    int gF4 = (NN * 32 + tb - 1) / tb;
    int gEw = (NE * 32 + tb - 1) / tb;

    // launch order keeps the scatter at position 4 for ncu visibility
    k_deg_init<<<gN, tb>>>();                                        // 1
    k_deg_edges<<<gE, tb>>>(row, col, ew);                           // 2
    k_prep<<<gF4, tb>>>((const float4*)x);                           // 3 (dis + layer-1 self-term)
    k_scatter<false><<<gEw, tb>>>((const float4*)x, row, col, ew);   // 4  <- profiled
    k_wprep<<<(2 * 16384 + tb - 1) / tb, tb>>>(W1, Wmu, Wls);        // 5
    k_mmagemm<0><<<NTILES, tb, SM_TOTAL>>>(b1, nullptr, nullptr, nullptr);  // 6 (+ layer-2 self-term)
    k_scatter<true><<<gEw, tb>>>(nullptr, row, col, ew);             // 7
    k_mmagemm<1><<<NTILES, tb, SM_TOTAL>>>(bmu, bls, mu, ls);        // 8
}